// round 2
// baseline (speedup 1.0000x reference)
#include <cuda_runtime.h>

static constexpr int AB    = 128;   // A*B = 8*16
static constexpr int NROWS = 1024;  // N = M
static constexpr int KD    = 64;

// Scratch: [0, AB*KD) = u_sum, [AB*KD, 2*AB*KD) = v_sum  (64 KB)
__device__ float g_sums[2 * AB * KD];

// ---------------------------------------------------------------------------
// Kernel 1: column sums over the row dimension for every (ab, tensor) slice.
// grid = 256 (128 ab-slices x {u,v}), block = 1024 = 16 rows x 64 k-lanes.
// Kahan-compensated sequential accumulation (64 terms/thread) + smem tree
// reduce across the 16 row-groups: keeps the sum error ~1e-5 so the sign
// gate matches the reference's tree-reduced sums.
// ---------------------------------------------------------------------------
__global__ void __launch_bounds__(1024) sums_kernel(const float* __restrict__ u,
                                                    const float* __restrict__ v) {
    const int b      = blockIdx.x;   // 0..255
    const int tensor = b >> 7;       // 0 = u, 1 = v
    const int ab     = b & 127;
    const float* __restrict__ base =
        (tensor ? v : u) + (size_t)ab * NROWS * KD;

    const int t = threadIdx.x;
    const int k = t & 63;
    const int r = t >> 6;            // 0..15

    float s = 0.f, c = 0.f;          // Kahan accumulator
#pragma unroll 8
    for (int row = r; row < NROWS; row += 16) {
        float x  = base[row * KD + k];
        float y  = x - c;
        float tt = s + y;
        c = (tt - s) - y;
        s = tt;
    }

    __shared__ float sred[16][KD];
    sred[r][k] = s;
    __syncthreads();
#pragma unroll
    for (int stride = 8; stride > 0; stride >>= 1) {
        if (r < stride) sred[r][k] += sred[r + stride][k];
        __syncthreads();
    }
    if (r == 0) g_sums[tensor * AB * KD + ab * KD + k] = sred[0][k];
}

// ---------------------------------------------------------------------------
// Kernel 2: one warp per row. Lane loads a float2 (elements k, k+1 with
// lane covering the 64-wide row as 32 float2s), dot with the opposite
// tensor's column-sum vector (L1-hot), xor-shuffle tree reduce, gate =
// relu(sign(.)) = (sum > 0), write gated row.
// Output layout: [gated u (8M floats) | gated v (8M floats)].
// ---------------------------------------------------------------------------
__global__ void __launch_bounds__(256) gate_kernel(const float2* __restrict__ u,
                                                   const float2* __restrict__ v,
                                                   float2* __restrict__ out) {
    const int lane = threadIdx.x & 31;
    const int wg   = (blockIdx.x * blockDim.x + threadIdx.x) >> 5;
    const int TOTAL = AB * NROWS;    // rows per tensor

    const float2* __restrict__ src;
    const float*  __restrict__ sums;
    float2* __restrict__ dst;
    int row;
    if (wg < TOTAL) {
        row  = wg;
        src  = u;
        dst  = out;
        sums = g_sums + AB * KD;     // u is gated by v_sum
    } else {
        row  = wg - TOTAL;
        src  = v;
        dst  = out + (size_t)TOTAL * (KD / 2);
        sums = g_sums;               // v is gated by u_sum
    }

    const int ab = row >> 10;        // row / NROWS
    const float2 x  = src[(size_t)row * (KD / 2) + lane];
    const float2 sv = __ldg(reinterpret_cast<const float2*>(sums + ab * KD) + lane);

    float p = fmaf(x.x, sv.x, x.y * sv.y);
#pragma unroll
    for (int m = 16; m; m >>= 1) p += __shfl_xor_sync(0xffffffffu, p, m);

    const float g = (p > 0.f) ? 1.f : 0.f;
    dst[(size_t)row * (KD / 2) + lane] = make_float2(x.x * g, x.y * g);
}

// ---------------------------------------------------------------------------
extern "C" void kernel_launch(void* const* d_in, const int* in_sizes, int n_in,
                              void* d_out, int out_size) {
    const float* u = (const float*)d_in[0];
    const float* v = (const float*)d_in[1];

    sums_kernel<<<256, 1024>>>(u, v);

    const int total_warps = 2 * AB * NROWS;        // 262144 rows total
    const int blocks      = total_warps / 8;       // 8 warps / 256-thread block
    gate_kernel<<<blocks, 256>>>((const float2*)u, (const float2*)v,
                                 (float2*)d_out);
}

// round 3
// speedup vs baseline: 1.2380x; 1.2380x over previous
#include <cuda_runtime.h>

static constexpr int AB    = 128;   // A*B = 8*16
static constexpr int NROWS = 1024;  // N = M
static constexpr int KD    = 64;

// Scratch: [0, AB*KD) = u_sum, [AB*KD, 2*AB*KD) = v_sum  (64 KB)
__device__ float g_sums[2 * AB * KD];

// ---------------------------------------------------------------------------
// Kernel 1: column sums over the row dimension for every (ab, tensor) slice.
// grid = 256 (128 ab-slices x {u,v}), block = 1024 = 16 rows x 64 k-lanes.
// Kahan-compensated accumulation + smem tree keeps sum error ~1e-5 so the
// sign gate matches the reference's tree-reduced sums. DRAM-bound; ALU chain
// hides under the 64 MB streaming read.
// ---------------------------------------------------------------------------
__global__ void __launch_bounds__(1024) sums_kernel(const float* __restrict__ u,
                                                    const float* __restrict__ v) {
    const int b      = blockIdx.x;   // 0..255
    const int tensor = b >> 7;       // 0 = u, 1 = v
    const int ab     = b & 127;
    const float* __restrict__ base =
        (tensor ? v : u) + (size_t)ab * NROWS * KD;

    const int t = threadIdx.x;
    const int k = t & 63;
    const int r = t >> 6;            // 0..15

    float s = 0.f, c = 0.f;          // Kahan accumulator
#pragma unroll 8
    for (int row = r; row < NROWS; row += 16) {
        float x  = base[row * KD + k];
        float y  = x - c;
        float tt = s + y;
        c = (tt - s) - y;
        s = tt;
    }

    __shared__ float sred[16][KD];
    sred[r][k] = s;
    __syncthreads();
#pragma unroll
    for (int stride = 8; stride > 0; stride >>= 1) {
        if (r < stride) sred[r][k] += sred[r + stride][k];
        __syncthreads();
    }
    if (r == 0) g_sums[tensor * AB * KD + ab * KD + k] = sred[0][k];
}

// ---------------------------------------------------------------------------
// Kernel 2 (v2): 8 rows per warp, float4, 4 independent slots.
//   lane: half = lane>>4 selects row within a slot pair, q = lane&15 is the
//   float4 index within the 64-float row.
//   4 slot loads issued back-to-back (MLP=4, 64B/lane outstanding), 4-level
//   xor-shuffle trees (masks 8,4,2,1 confined to the 16-lane segment)
//   interleaved across slots to overlap SHFL latency.
// Output layout: [gated u | gated v], each 8M floats.
// ---------------------------------------------------------------------------
__global__ void __launch_bounds__(256) gate_kernel(const float4* __restrict__ u,
                                                   const float4* __restrict__ v,
                                                   float4* __restrict__ out) {
    const int lane = threadIdx.x & 31;
    const int w    = (blockIdx.x * blockDim.x + threadIdx.x) >> 5;  // 0..32767

    static constexpr int ROWS_T  = AB * NROWS;        // rows per tensor (131072)
    static constexpr int WARPS_T = ROWS_T / 8;        // 16384 warps per tensor
    static constexpr int RQ      = KD / 4;            // float4 per row (16)

    const float4* __restrict__ src;
    const float*  __restrict__ sums;
    float4* __restrict__ dst;
    int wrow;
    if (w < WARPS_T) {
        wrow = w;                src = u;  dst = out;
        sums = g_sums + AB * KD;          // u gated by v_sum
    } else {
        wrow = w - WARPS_T;      src = v;  dst = out + (size_t)ROWS_T * RQ;
        sums = g_sums;                    // v gated by u_sum
    }

    const int row0 = wrow * 8;            // 8 contiguous rows, never cross ab
    const int ab   = row0 >> 10;
    const int half = lane >> 4;           // row parity within a slot
    const int q    = lane & 15;           // float4 column

    const float4 sv =
        __ldg(reinterpret_cast<const float4*>(sums + ab * KD) + q);

    const size_t base = (size_t)row0 * RQ + (size_t)half * RQ + q;

    float4 x[4];
#pragma unroll
    for (int j = 0; j < 4; j++) x[j] = src[base + (size_t)j * (2 * RQ)];

    float p[4];
#pragma unroll
    for (int j = 0; j < 4; j++)
        p[j] = fmaf(x[j].x, sv.x,
                fmaf(x[j].y, sv.y,
                 fmaf(x[j].z, sv.z, x[j].w * sv.w)));

#pragma unroll
    for (int m = 8; m; m >>= 1)
#pragma unroll
        for (int j = 0; j < 4; j++)
            p[j] += __shfl_xor_sync(0xffffffffu, p[j], m);

#pragma unroll
    for (int j = 0; j < 4; j++) {
        const float g = (p[j] > 0.f) ? 1.f : 0.f;
        dst[base + (size_t)j * (2 * RQ)] =
            make_float4(x[j].x * g, x[j].y * g, x[j].z * g, x[j].w * g);
    }
}

// ---------------------------------------------------------------------------
extern "C" void kernel_launch(void* const* d_in, const int* in_sizes, int n_in,
                              void* d_out, int out_size) {
    const float* u = (const float*)d_in[0];
    const float* v = (const float*)d_in[1];

    sums_kernel<<<256, 1024>>>(u, v);

    // 2 tensors * 131072 rows / 8 rows-per-warp = 32768 warps = 4096 blocks
    gate_kernel<<<4096, 256>>>((const float4*)u, (const float4*)v,
                               (float4*)d_out);
}

// round 4
// speedup vs baseline: 1.3282x; 1.0728x over previous
#include <cuda_runtime.h>

static constexpr int AB     = 128;   // A*B = 8*16
static constexpr int NROWS  = 1024;  // N = M
static constexpr int KD     = 64;
static constexpr int RQ     = KD / 4;   // float4 per row = 16
static constexpr int CHUNKS = 4;        // row-chunks per slice (256 rows each)

// Chunk partial sums: [tensor][ab][chunk][q]  (q = float4 column), 64 KB
__device__ float4 g_part[2 * AB * CHUNKS * RQ];

// ---------------------------------------------------------------------------
// Kernel 1 (v3): per-chunk column sums. grid = 1024 blocks (2 tensors x 128
// ab x 4 chunks), block = 256 = 16 row-groups x 16 float4-lanes. Each thread
// accumulates 16 float4s (independent loads, MLP=16, plain FADD — per-thread
// partials are 16-element sums, error ~1e-6), then a 4-level smem tree.
// Gate kernel finishes the reduction by summing the 4 chunk partials.
// ---------------------------------------------------------------------------
__global__ void __launch_bounds__(256) sums_kernel(const float4* __restrict__ u,
                                                   const float4* __restrict__ v) {
    const int b      = blockIdx.x;       // 0..1023
    const int tensor = b >> 9;           // 0 = u, 1 = v
    const int rem    = b & 511;          // ab*4 + chunk
    const int ab     = rem >> 2;
    const int chunk  = rem & 3;

    const float4* __restrict__ base =
        (tensor ? v : u) + ((size_t)ab * NROWS + chunk * 256) * RQ;

    const int q = threadIdx.x & 15;      // float4 column
    const int r = threadIdx.x >> 4;      // 0..15 row-group

    float4 s = make_float4(0.f, 0.f, 0.f, 0.f);
#pragma unroll
    for (int i = 0; i < 16; i++) {
        const float4 x = base[(size_t)(r + i * 16) * RQ + q];
        s.x += x.x; s.y += x.y; s.z += x.z; s.w += x.w;
    }

    __shared__ float4 sred[16][RQ];
    sred[r][q] = s;
    __syncthreads();
#pragma unroll
    for (int stride = 8; stride > 0; stride >>= 1) {
        if (r < stride) {
            const float4 o = sred[r + stride][q];
            sred[r][q].x += o.x; sred[r][q].y += o.y;
            sred[r][q].z += o.z; sred[r][q].w += o.w;
        }
        __syncthreads();
    }
    if (r == 0)
        g_part[((tensor * AB + ab) * CHUNKS + chunk) * RQ + q] = sred[0][q];
}

// ---------------------------------------------------------------------------
// Kernel 2 (v3): 16 rows per warp, float4, 8 independent slots.
//   half = lane>>4 picks the row within a slot pair, q = lane&15 the float4
//   column. 8 loads issued back-to-back (128B/lane outstanding), 8
//   interleaved 4-level xor-shuffle trees (masks 8..1 stay in the 16-lane
//   segment). sv assembled from the 4 L1-hot chunk partials.
// Output layout: [gated u | gated v], each 8M floats.
// ---------------------------------------------------------------------------
__global__ void __launch_bounds__(256) gate_kernel(const float4* __restrict__ u,
                                                   const float4* __restrict__ v,
                                                   float4* __restrict__ out) {
    const int lane = threadIdx.x & 31;
    const int w    = (blockIdx.x * blockDim.x + threadIdx.x) >> 5;  // 0..16383

    static constexpr int ROWS_T  = AB * NROWS;       // 131072 rows per tensor
    static constexpr int WARPS_T = ROWS_T / 16;      // 8192 warps per tensor

    const float4* __restrict__ src;
    const float4* __restrict__ part;
    float4* __restrict__ dst;
    int wrow;
    if (w < WARPS_T) {
        wrow = w;            src = u;  dst = out;
        part = g_part + (size_t)1 * AB * CHUNKS * RQ;   // u gated by v_sum
    } else {
        wrow = w - WARPS_T;  src = v;  dst = out + (size_t)ROWS_T * RQ;
        part = g_part;                                   // v gated by u_sum
    }

    const int row0 = wrow * 16;          // 16 contiguous rows; 1024%16==0 so
    const int ab   = row0 >> 10;         // a warp never crosses an ab slice
    const int half = lane >> 4;
    const int q    = lane & 15;

    // sv = sum of the 4 chunk partials (all L1/L2-hot)
    const float4* __restrict__ P = part + (size_t)ab * CHUNKS * RQ + q;
    float4 sv = __ldg(P);
#pragma unroll
    for (int c = 1; c < CHUNKS; c++) {
        const float4 o = __ldg(P + c * RQ);
        sv.x += o.x; sv.y += o.y; sv.z += o.z; sv.w += o.w;
    }

    const size_t base = (size_t)row0 * RQ + (size_t)half * RQ + q;

    float4 x[8];
#pragma unroll
    for (int j = 0; j < 8; j++) x[j] = src[base + (size_t)j * (2 * RQ)];

    float p[8];
#pragma unroll
    for (int j = 0; j < 8; j++)
        p[j] = fmaf(x[j].x, sv.x,
                fmaf(x[j].y, sv.y,
                 fmaf(x[j].z, sv.z, x[j].w * sv.w)));

#pragma unroll
    for (int m = 8; m; m >>= 1)
#pragma unroll
        for (int j = 0; j < 8; j++)
            p[j] += __shfl_xor_sync(0xffffffffu, p[j], m);

#pragma unroll
    for (int j = 0; j < 8; j++) {
        const float g = (p[j] > 0.f) ? 1.f : 0.f;
        dst[base + (size_t)j * (2 * RQ)] =
            make_float4(x[j].x * g, x[j].y * g, x[j].z * g, x[j].w * g);
    }
}

// ---------------------------------------------------------------------------
extern "C" void kernel_launch(void* const* d_in, const int* in_sizes, int n_in,
                              void* d_out, int out_size) {
    const float* u = (const float*)d_in[0];
    const float* v = (const float*)d_in[1];

    sums_kernel<<<2 * AB * CHUNKS, 256>>>((const float4*)u, (const float4*)v);

    // 2 tensors * 131072 rows / 16 rows-per-warp = 16384 warps = 2048 blocks
    gate_kernel<<<2048, 256>>>((const float4*)u, (const float4*)v,
                               (float4*)d_out);
}

// round 5
// speedup vs baseline: 1.5289x; 1.1511x over previous
#include <cuda_runtime.h>

static constexpr int AB    = 128;    // A*B
static constexpr int NROWS = 1024;   // N = M
static constexpr int KD    = 64;
static constexpr int RQ    = KD / 4; // float4 per row = 16
static constexpr int CHV   = 4;      // v-sum chunks per ab (256 rows each)
static constexpr int CHU   = 8;      // u-sum chunks per ab (128 rows each)

// Partial column sums (fixed-order, deterministic)
__device__ float4 g_part_v[AB * CHV * RQ];   // [ab][chunk][q]
__device__ float4 g_part_u[AB * CHU * RQ];   // [ab][chunk][q]

// ---------------------------------------------------------------------------
// K1: v column sums. grid = 512 (128 ab x 4 chunks), block = 256 =
// 16 row-groups x 16 float4-lanes. 16 independent float4 loads per thread,
// then 4-level smem tree. Default cache policy: v must STAY in L2 for K3.
// ---------------------------------------------------------------------------
__global__ void __launch_bounds__(256) vsum_kernel(const float4* __restrict__ v) {
    const int b     = blockIdx.x;      // 0..511
    const int ab    = b >> 2;
    const int chunk = b & 3;
    const float4* __restrict__ base = v + ((size_t)ab * NROWS + chunk * 256) * RQ;

    const int q = threadIdx.x & 15;
    const int r = threadIdx.x >> 4;    // 0..15

    float4 s = make_float4(0.f, 0.f, 0.f, 0.f);
#pragma unroll
    for (int i = 0; i < 16; i++) {
        const float4 x = base[(size_t)(r + i * 16) * RQ + q];
        s.x += x.x; s.y += x.y; s.z += x.z; s.w += x.w;
    }

    __shared__ float4 sred[16][RQ];
    sred[r][q] = s;
    __syncthreads();
#pragma unroll
    for (int stride = 8; stride > 0; stride >>= 1) {
        if (r < stride) {
            const float4 o = sred[r + stride][q];
            sred[r][q].x += o.x; sred[r][q].y += o.y;
            sred[r][q].z += o.z; sred[r][q].w += o.w;
        }
        __syncthreads();
    }
    if (r == 0) g_part_v[(ab * CHV + chunk) * RQ + q] = sred[0][q];
}

// ---------------------------------------------------------------------------
// K2: single pass over u. Per warp: 16 rows (8 float4 slots, half=lane>>4,
// q=lane&15). Computes (a) row dots vs v_sum -> gate -> streamed store of
// gated u; (b) this block's 128-row column partial -> g_part_u.
// grid = 1024 (128 ab x 8 chunks), block = 256 (8 warps x 16 rows).
// u is read exactly once ever -> __ldcs (evict-first, preserves L2 for v).
// ---------------------------------------------------------------------------
__global__ void __launch_bounds__(256) usum_gateu_kernel(const float4* __restrict__ u,
                                                         float4* __restrict__ out) {
    const int blk   = blockIdx.x;       // 0..1023
    const int ab    = blk >> 3;
    const int chunk = blk & 7;
    const int warp  = threadIdx.x >> 5; // 0..7
    const int lane  = threadIdx.x & 31;
    const int half  = lane >> 4;
    const int q     = lane & 15;

    // v_sum[ab] from its 4 chunk partials (L2-hot, tiny)
    const float4* __restrict__ Pv = g_part_v + (size_t)ab * CHV * RQ + q;
    float4 sv = __ldg(Pv);
#pragma unroll
    for (int c = 1; c < CHV; c++) {
        const float4 o = __ldg(Pv + c * RQ);
        sv.x += o.x; sv.y += o.y; sv.z += o.z; sv.w += o.w;
    }

    const int    row0 = ab * NROWS + chunk * 128 + warp * 16;
    const size_t base = (size_t)row0 * RQ + (size_t)half * RQ + q;

    float4 x[8];
#pragma unroll
    for (int j = 0; j < 8; j++) x[j] = __ldcs(u + base + (size_t)j * (2 * RQ));

    // (b) column partial: per-lane sum over the 8 slots, then fold halves
    float4 cs = make_float4(0.f, 0.f, 0.f, 0.f);
#pragma unroll
    for (int j = 0; j < 8; j++) {
        cs.x += x[j].x; cs.y += x[j].y; cs.z += x[j].z; cs.w += x[j].w;
    }
    cs.x += __shfl_xor_sync(0xffffffffu, cs.x, 16);
    cs.y += __shfl_xor_sync(0xffffffffu, cs.y, 16);
    cs.z += __shfl_xor_sync(0xffffffffu, cs.z, 16);
    cs.w += __shfl_xor_sync(0xffffffffu, cs.w, 16);

    __shared__ float4 sred[8][RQ];     // per-warp 16-row partials
    if (half == 0) sred[warp][q] = cs;
    __syncthreads();
    if (threadIdx.x < 16) {            // serial 8-term sum, fixed order
        float4 a = sred[0][q];
#pragma unroll
        for (int wgi = 1; wgi < 8; wgi++) {
            const float4 o = sred[wgi][q];
            a.x += o.x; a.y += o.y; a.z += o.z; a.w += o.w;
        }
        g_part_u[(ab * CHU + chunk) * RQ + q] = a;
    }

    // (a) gate: row dot vs sv, 4-level xor tree inside the 16-lane segment
    float p[8];
#pragma unroll
    for (int j = 0; j < 8; j++)
        p[j] = fmaf(x[j].x, sv.x,
                fmaf(x[j].y, sv.y,
                 fmaf(x[j].z, sv.z, x[j].w * sv.w)));
#pragma unroll
    for (int m = 8; m; m >>= 1)
#pragma unroll
        for (int j = 0; j < 8; j++)
            p[j] += __shfl_xor_sync(0xffffffffu, p[j], m);

#pragma unroll
    for (int j = 0; j < 8; j++) {
        const float g = (p[j] > 0.f) ? 1.f : 0.f;
        __stcs(out + base + (size_t)j * (2 * RQ),
               make_float4(x[j].x * g, x[j].y * g, x[j].z * g, x[j].w * g));
    }
}

// ---------------------------------------------------------------------------
// K3: gate v with u_sum. Same warp layout as K2 minus the partial-sum work.
// v reads should be L2-hot (K1 streamed it; K2's u was evict-first).
// grid = 1024, block = 256.
// ---------------------------------------------------------------------------
__global__ void __launch_bounds__(256) gatev_kernel(const float4* __restrict__ v,
                                                    float4* __restrict__ outv) {
    const int blk   = blockIdx.x;
    const int ab    = blk >> 3;
    const int chunk = blk & 7;
    const int warp  = threadIdx.x >> 5;
    const int lane  = threadIdx.x & 31;
    const int half  = lane >> 4;
    const int q     = lane & 15;

    // u_sum[ab] from its 8 chunk partials
    const float4* __restrict__ Pu = g_part_u + (size_t)ab * CHU * RQ + q;
    float4 su = __ldg(Pu);
#pragma unroll
    for (int c = 1; c < CHU; c++) {
        const float4 o = __ldg(Pu + c * RQ);
        su.x += o.x; su.y += o.y; su.z += o.z; su.w += o.w;
    }

    const int    row0 = ab * NROWS + chunk * 128 + warp * 16;
    const size_t base = (size_t)row0 * RQ + (size_t)half * RQ + q;

    float4 x[8];
#pragma unroll
    for (int j = 0; j < 8; j++) x[j] = __ldcs(v + base + (size_t)j * (2 * RQ));

    float p[8];
#pragma unroll
    for (int j = 0; j < 8; j++)
        p[j] = fmaf(x[j].x, su.x,
                fmaf(x[j].y, su.y,
                 fmaf(x[j].z, su.z, x[j].w * su.w)));
#pragma unroll
    for (int m = 8; m; m >>= 1)
#pragma unroll
        for (int j = 0; j < 8; j++)
            p[j] += __shfl_xor_sync(0xffffffffu, p[j], m);

#pragma unroll
    for (int j = 0; j < 8; j++) {
        const float g = (p[j] > 0.f) ? 1.f : 0.f;
        __stcs(outv + base + (size_t)j * (2 * RQ),
               make_float4(x[j].x * g, x[j].y * g, x[j].z * g, x[j].w * g));
    }
}

// ---------------------------------------------------------------------------
extern "C" void kernel_launch(void* const* d_in, const int* in_sizes, int n_in,
                              void* d_out, int out_size) {
    const float4* u = (const float4*)d_in[0];
    const float4* v = (const float4*)d_in[1];
    float4* out  = (float4*)d_out;
    float4* outv = out + (size_t)AB * NROWS * RQ;   // second half: gated v

    vsum_kernel      <<<AB * CHV, 256>>>(v);
    usum_gateu_kernel<<<AB * CHU, 256>>>(u, out);
    gatev_kernel     <<<AB * CHU, 256>>>(v, outv);
}